// round 14
// baseline (speedup 1.0000x reference)
#include <cuda_runtime.h>
#include <cuda_fp16.h>

// QuantizedBatchNorm3d: x [8,64,32,64,64] fp32, weight[64], bias[64] -> y same shape.
// fake_quant(exp=5, sig=10, RNE) == IEEE fp16 round-trip for all reachable values.
//
// R14: fused tile pipeline. Grid = 4 x SM-count (uniform 4 blocks/SM, queried at
// launch) striding 8192 tiles of 32KB. Phase 1: per-tile reduce -> slot; channel
// counter (acq_rel); completing block publishes params (release flag). Phase 2:
// tiles in EXACT REVERSE global order (channel/offset descending) -> consumes
// L2 residual freshest-first; acquire-spin only at the channel-63 frontier
// (~one tile). No coarse barrier, no SM-imbalance skew, replay-deterministic.

#define NC       64
#define CPC      (1 << 20)            // elements per channel
#define THREADS  512
#define NT       8192                 // tiles (2048 float4 = 32KB each)
#define TPC      128                  // tiles per channel

__device__ float    g_tsum[NT];
__device__ float    g_tsq [NT];
__device__ float4   g_params[NC];     // {mean_q, inv_std, w_q, b_q}
__device__ unsigned g_cnt [NC];       // phase-1 tiles done   (reset by handshake)
__device__ unsigned g_flag[NC];       // params published
__device__ unsigned g_done[NC];       // phase-2 tiles done

__device__ __forceinline__ float fq1(float v) {
    return __half2float(__float2half_rn(v));
}
__device__ __forceinline__ float2 fq2(float a, float b) {
    __half2 h = __floats2half2_rn(a, b);
    return __half22float2(h);
}

__global__ void __launch_bounds__(THREADS, 4)
qbn_fused(const float* __restrict__ x,
          const float* __restrict__ weight,
          const float* __restrict__ bias,
          float* __restrict__ out) {
    __shared__ float  sh_s[16], sh_q[16];
    __shared__ int    sh_do;
    __shared__ float4 sh_p;

    const int b = blockIdx.x, t = threadIdx.x;
    const int lane = t & 31, w = t >> 5;
    const int stride = gridDim.x;
    const float4* x4 = reinterpret_cast<const float4*>(x);
    float4*       o4 = reinterpret_cast<float4*>(out);

    // ----------------- Phase 1: strided tiles, ascending order -----------------
    for (int T = b; T < NT; T += stride) {
        const int c = T >> 7, r = T & 127;                 // channel, tile-in-channel
        const size_t base = ((size_t)((r >> 4) * NC + c) << 15)
                          + ((size_t)(r & 15) << 11);       // [n][c][spatial] layout
        float4 v[4];
        #pragma unroll
        for (int k = 0; k < 4; k++) v[k] = x4[base + k * THREADS + t];

        float s = 0.f, sq = 0.f;
        #pragma unroll
        for (int k = 0; k < 4; k++) {
            float2 a = fq2(v[k].x, v[k].y), d = fq2(v[k].z, v[k].w);
            s  += (a.x + a.y) + (d.x + d.y);
            sq += a.x*a.x + a.y*a.y + d.x*d.x + d.y*d.y;
        }
        #pragma unroll
        for (int o = 16; o > 0; o >>= 1) {
            s  += __shfl_down_sync(0xffffffffu, s,  o);
            sq += __shfl_down_sync(0xffffffffu, sq, o);
        }
        if (lane == 0) { sh_s[w] = s; sh_q[w] = sq; }
        __syncthreads();
        if (t == 0) {
            float ss = 0.f, qq = 0.f;
            #pragma unroll
            for (int i = 0; i < 16; i++) { ss += sh_s[i]; qq += sh_q[i]; }
            g_tsum[T] = ss;
            g_tsq [T] = qq;
            unsigned old;
            asm volatile("atom.acq_rel.gpu.global.add.u32 %0, [%1], %2;"
                         : "=r"(old) : "l"(&g_cnt[c]), "r"(1u) : "memory");
            sh_do = (old == TPC - 1) ? c : -1;
        }
        __syncthreads();

        const int fc = sh_do;                 // uniform across block
        if (fc >= 0) {                        // this block completed channel fc
            float ss = 0.f, qq = 0.f;
            if (t < TPC) {
                ss = g_tsum[fc * TPC + t];
                qq = g_tsq [fc * TPC + t];
                #pragma unroll
                for (int o = 16; o > 0; o >>= 1) {
                    ss += __shfl_down_sync(0xffffffffu, ss, o);
                    qq += __shfl_down_sync(0xffffffffu, qq, o);
                }
                if (lane == 0) { sh_s[w] = ss; sh_q[w] = qq; }
            }
            __syncthreads();
            if (t == 0) {
                ss = sh_s[0] + sh_s[1] + sh_s[2] + sh_s[3];
                qq = sh_q[0] + sh_q[1] + sh_q[2] + sh_q[3];
                const float inv_n = 1.0f / (float)CPC;
                float mean = ss * inv_n;
                float var  = qq * inv_n - mean * mean;
                float mean_q  = fq1(mean);
                float var_q   = fq1(var);
                float inv_std = 1.0f / sqrtf(var_q + 1e-5f);
                g_params[fc] = make_float4(mean_q, inv_std,
                                           fq1(weight[fc]), fq1(bias[fc]));
                asm volatile("st.release.gpu.global.u32 [%0], %1;"
                             :: "l"(&g_flag[fc]), "r"(1u) : "memory");
            }
            __syncthreads();
        }
    }

    // --------- Phase 2: exact reverse global order (freshest L2 first) ---------
    for (int U = b; U < NT; U += stride) {
        const int c = (NC - 1) - (U >> 7);
        const int r = (TPC - 1) - (U & 127);
        const size_t base = ((size_t)((r >> 4) * NC + c) << 15)
                          + ((size_t)(r & 15) << 11);

        if (t == 0) {
            unsigned f;
            for (;;) {
                asm volatile("ld.acquire.gpu.global.u32 %0, [%1];"
                             : "=r"(f) : "l"(&g_flag[c]) : "memory");
                if (f) break;
                __nanosleep(128);
            }
            sh_p = g_params[c];               // ordered after acquire
        }
        __syncthreads();
        const float4 p = sh_p;                // {mean, inv_std, w, b}

        float4 v[4];
        #pragma unroll
        for (int k = 0; k < 4; k++)
            v[k] = __ldcs(x4 + base + k * THREADS + t);
        #pragma unroll
        for (int k = 0; k < 4; k++) {
            float2 a = fq2(v[k].x, v[k].y), d = fq2(v[k].z, v[k].w);
            float y0 = fmaf(p.z, (a.x - p.x) * p.y, p.w);
            float y1 = fmaf(p.z, (a.y - p.x) * p.y, p.w);
            float y2 = fmaf(p.z, (d.x - p.x) * p.y, p.w);
            float y3 = fmaf(p.z, (d.y - p.x) * p.y, p.w);
            float2 q0 = fq2(y0, y1), q1 = fq2(y2, y3);
            __stcs(o4 + base + k * THREADS + t,
                   make_float4(q0.x, q0.y, q1.x, q1.y));
        }
        __syncthreads();
        if (t == 0) {
            unsigned old = atomicAdd(&g_done[c], 1u);
            if (old == TPC - 1) {             // last phase-2 tile of channel c:
                g_cnt[c]  = 0u;               // reclaim counters for next replay
                g_flag[c] = 0u;
                g_done[c] = 0u;
            }
        }
    }
}

extern "C" void kernel_launch(void* const* d_in, const int* in_sizes, int n_in,
                              void* d_out, int out_size) {
    const float* x      = (const float*)d_in[0];
    const float* weight = (const float*)d_in[1];
    const float* bias   = (const float*)d_in[2];
    float* out = (float*)d_out;

    static int nblocks = 0;
    if (nblocks == 0) {
        int sms = 0;
        cudaDeviceGetAttribute(&sms, cudaDevAttrMultiProcessorCount, 0);
        nblocks = 4 * sms;                    // uniform 4 blocks on every SM
    }
    qbn_fused<<<nblocks, THREADS>>>(x, weight, bias, out);
}

// round 15
// speedup vs baseline: 1.1134x; 1.1134x over previous
#include <cuda_runtime.h>
#include <cuda_fp16.h>

// QuantizedBatchNorm3d: x [8,64,32,64,64] fp32, weight[64], bias[64] -> y same shape.
// fake_quant(exp=5, sig=10, RNE) == IEEE fp16 round-trip for all reachable values.
//
// R15: staggered channel-interleave, one fused kernel. Block b (1024 blocks,
// co-resident @7/SM) owns 8 segments of 2048 float4, one in each channel
// c0+8k (c0=b>>7, sibling m=b&127 of 128). Phase 1 reduces segments ascending
// k -> channel c0+8k complete at ~(k+1)/16 of kernel time. Phase 2 applies in
// order {6,7,5,4,3,2,1,0}: every channel is ready before it's needed (no
// barrier idle), and the freshest segments (6,7) are re-read first (L2 hits).

#define NC      64
#define CPC     (1 << 20)             // elements per channel
#define NBLK    1024
#define NTHR    256
#define SIBS    128                   // sibling blocks per channel
#define SEG_F4  2048                  // float4 per (block, channel) segment

__device__ float    g_psum[NC * SIBS];
__device__ float    g_psq [NC * SIBS];
__device__ float4   g_params[NC];
__device__ unsigned g_cnt [NC];       // phase-1 partials counted (reset by handshake)
__device__ unsigned g_flag[NC];       // params published
__device__ unsigned g_done[NC];       // phase-2 segments counted

__device__ __forceinline__ float fq1(float v) {
    return __half2float(__float2half_rn(v));
}
__device__ __forceinline__ float2 fq2(float a, float b) {
    __half2 h = __floats2half2_rn(a, b);
    return __half22float2(h);
}

__global__ void __launch_bounds__(NTHR, 7)
qbn_fused(const float* __restrict__ x,
          const float* __restrict__ weight,
          const float* __restrict__ bias,
          float* __restrict__ out) {
    __shared__ float  sh_s[8], sh_q[8];
    __shared__ int    sh_fin;
    __shared__ float4 sh_p[2];

    const int b = blockIdx.x, t = threadIdx.x;
    const int lane = t & 31, w = t >> 5;
    const int c0 = b >> 7;            // channel group [0,8)
    const int m  = b & (SIBS - 1);    // sibling index within each channel
    const int n  = m >> 4;            // batch slice
    const size_t soff = ((size_t)(m & 15)) << 11;   // offset inside (n,c) slice

    const float4* x4 = reinterpret_cast<const float4*>(x);
    float4*       o4 = reinterpret_cast<float4*>(out);

    // ---------------- Phase 1: 8 segments, channels ascending ----------------
    #pragma unroll 1
    for (int k = 0; k < 8; k++) {
        const int c = c0 + 8 * k;
        const size_t base = (((size_t)(n * NC + c)) << 15) + soff;

        float s = 0.f, sq = 0.f;
        #pragma unroll
        for (int h = 0; h < 2; h++) {
            float4 v[4];
            #pragma unroll
            for (int j = 0; j < 4; j++)
                v[j] = x4[base + (h * 4 + j) * NTHR + t];
            #pragma unroll
            for (int j = 0; j < 4; j++) {
                float2 a = fq2(v[j].x, v[j].y), d = fq2(v[j].z, v[j].w);
                s  += (a.x + a.y) + (d.x + d.y);
                sq += a.x*a.x + a.y*a.y + d.x*d.x + d.y*d.y;
            }
        }
        #pragma unroll
        for (int o = 16; o > 0; o >>= 1) {
            s  += __shfl_down_sync(0xffffffffu, s,  o);
            sq += __shfl_down_sync(0xffffffffu, sq, o);
        }
        if (lane == 0) { sh_s[w] = s; sh_q[w] = sq; }
        __syncthreads();
        if (t == 0) {
            float ss = 0.f, qq = 0.f;
            #pragma unroll
            for (int i = 0; i < 8; i++) { ss += sh_s[i]; qq += sh_q[i]; }
            g_psum[c * SIBS + m] = ss;
            g_psq [c * SIBS + m] = qq;
            unsigned old;
            asm volatile("atom.acq_rel.gpu.global.add.u32 %0, [%1], %2;"
                         : "=r"(old) : "l"(&g_cnt[c]), "r"(1u) : "memory");
            sh_fin = (old == SIBS - 1) ? c : -1;
        }
        __syncthreads();

        const int fc = sh_fin;
        if (fc >= 0 && w == 0) {      // warp 0 finalizes channel fc (others run on)
            float ss = 0.f, qq = 0.f;
            #pragma unroll
            for (int i = 0; i < 4; i++) {
                ss += g_psum[fc * SIBS + lane + 32 * i];
                qq += g_psq [fc * SIBS + lane + 32 * i];
            }
            #pragma unroll
            for (int o = 16; o > 0; o >>= 1) {
                ss += __shfl_down_sync(0xffffffffu, ss, o);
                qq += __shfl_down_sync(0xffffffffu, qq, o);
            }
            if (lane == 0) {
                const float inv_n = 1.0f / (float)CPC;
                float mean = ss * inv_n;
                float var  = qq * inv_n - mean * mean;
                float mean_q  = fq1(mean);
                float var_q   = fq1(var);
                float inv_std = 1.0f / sqrtf(var_q + 1e-5f);
                g_params[fc] = make_float4(mean_q, inv_std,
                                           fq1(weight[fc]), fq1(bias[fc]));
                asm volatile("st.release.gpu.global.u32 [%0], %1;"
                             :: "l"(&g_flag[fc]), "r"(1u) : "memory");
            }
        }
    }

    // --------- Phase 2: apply segments, channel order {6,7,5,4,3,2,1,0} ---------
    const int ORD[8] = {6, 7, 5, 4, 3, 2, 1, 0};
    #pragma unroll 1
    for (int i = 0; i < 8; i++) {
        const int c = c0 + 8 * ORD[i];
        const size_t base = (((size_t)(n * NC + c)) << 15) + soff;

        // Batch A loads first (independent of params) to overlap the flag wait.
        float4 va[4];
        #pragma unroll
        for (int j = 0; j < 4; j++)
            va[j] = __ldcs(x4 + base + j * NTHR + t);

        if (t == 0) {
            unsigned f;
            for (;;) {
                asm volatile("ld.acquire.gpu.global.u32 %0, [%1];"
                             : "=r"(f) : "l"(&g_flag[c]) : "memory");
                if (f) break;
                __nanosleep(128);
            }
            sh_p[i & 1] = g_params[c];
        }
        __syncthreads();
        const float4 p = sh_p[i & 1];   // {mean, inv_std, w, b}

        #pragma unroll
        for (int j = 0; j < 4; j++) {
            float2 a = fq2(va[j].x, va[j].y), d = fq2(va[j].z, va[j].w);
            float y0 = fmaf(p.z, (a.x - p.x) * p.y, p.w);
            float y1 = fmaf(p.z, (a.y - p.x) * p.y, p.w);
            float y2 = fmaf(p.z, (d.x - p.x) * p.y, p.w);
            float y3 = fmaf(p.z, (d.y - p.x) * p.y, p.w);
            float2 q0 = fq2(y0, y1), q1 = fq2(y2, y3);
            __stcs(o4 + base + j * NTHR + t, make_float4(q0.x, q0.y, q1.x, q1.y));
        }
        float4 vb[4];
        #pragma unroll
        for (int j = 0; j < 4; j++)
            vb[j] = __ldcs(x4 + base + (4 + j) * NTHR + t);
        #pragma unroll
        for (int j = 0; j < 4; j++) {
            float2 a = fq2(vb[j].x, vb[j].y), d = fq2(vb[j].z, vb[j].w);
            float y0 = fmaf(p.z, (a.x - p.x) * p.y, p.w);
            float y1 = fmaf(p.z, (a.y - p.x) * p.y, p.w);
            float y2 = fmaf(p.z, (d.x - p.x) * p.y, p.w);
            float y3 = fmaf(p.z, (d.y - p.x) * p.y, p.w);
            float2 q0 = fq2(y0, y1), q1 = fq2(y2, y3);
            __stcs(o4 + base + (4 + j) * NTHR + t, make_float4(q0.x, q0.y, q1.x, q1.y));
        }

        if (t == 0) {
            unsigned old = atomicAdd(&g_done[c], 1u);
            if (old == SIBS - 1) {      // last sibling: reclaim for next replay
                g_cnt[c]  = 0u;
                g_flag[c] = 0u;
                g_done[c] = 0u;
            }
        }
    }
}

extern "C" void kernel_launch(void* const* d_in, const int* in_sizes, int n_in,
                              void* d_out, int out_size) {
    const float* x      = (const float*)d_in[0];
    const float* weight = (const float*)d_in[1];
    const float* bias   = (const float*)d_in[2];
    float* out = (float*)d_out;

    qbn_fused<<<NBLK, NTHR>>>(x, weight, bias, out);
}

// round 16
// speedup vs baseline: 1.1739x; 1.0543x over previous
#include <cuda_runtime.h>
#include <cuda_fp16.h>

// QuantizedBatchNorm3d: x [8,64,32,64,64] fp32, weight[64], bias[64] -> y same shape.
// fake_quant(exp=5, sig=10, RNE) == IEEE fp16 round-trip for all reachable values.
//
// R16: fused kernel with DYNAMIC TICKET scheduling. Blocks pull 2048-float4
// tiles from a global counter (one-ahead, latency hidden) -> perfect load
// balance across SMs regardless of residency imbalance; phase-1 tail skew ~1
// tile. Phase 1 sweeps tiles ascending; slot-indexed partials keep results
// deterministic under dynamic assignment; the 128th tile of a channel
// finalizes params (release flag). Phase 2 pulls from a second counter in
// EXACT REVERSE order (freshest L2 lines first, ~R11's self-harvest); flag
// spin exists only at the phase frontier and is hidden behind pre-issued
// loads. Last-exiting block resets all counters (replay-deterministic).

#define NC    64
#define CPC   (1 << 20)              // elements per channel
#define NTHR  256
#define NT    8192                   // tiles of 2048 float4 (32KB)
#define TPC   128                    // tiles per channel

__device__ float    g_tsum[NT];
__device__ float    g_tsq [NT];
__device__ float4   g_params[NC];
__device__ unsigned g_tick1, g_tick2, g_fin;   // zero-init; self-resetting
__device__ unsigned g_cnt [NC];
__device__ unsigned g_flag[NC];

__device__ __forceinline__ float fq1(float v) {
    return __half2float(__float2half_rn(v));
}
__device__ __forceinline__ float2 fq2(float a, float b) {
    __half2 h = __floats2half2_rn(a, b);
    return __half22float2(h);
}
__device__ __forceinline__ size_t tile_base(int T) {
    const int c = T >> 7, r = T & 127;
    return ((size_t)((r >> 4) * NC + c) << 15) + ((size_t)(r & 15) << 11);
}

__global__ void __launch_bounds__(NTHR)
qbn_fused(const float* __restrict__ x,
          const float* __restrict__ weight,
          const float* __restrict__ bias,
          float* __restrict__ out) {
    __shared__ float    sh_s[8], sh_q[8];
    __shared__ unsigned sh_T[2];
    __shared__ int      sh_fin;
    __shared__ float4   sh_p[2];

    const int t = threadIdx.x;
    const int lane = t & 31, w = t >> 5;
    const float4* x4 = reinterpret_cast<const float4*>(x);
    float4*       o4 = reinterpret_cast<float4*>(out);

    // ---------------- Phase 1: ascending tile sweep (dynamic) ----------------
    if (t == 0) sh_T[0] = atomicAdd(&g_tick1, 1u);
    __syncthreads();

    for (int it = 0; ; it++) {
        const int q = it & 1;
        const unsigned T = sh_T[q];
        if (T >= NT) break;
        const int c = (int)T >> 7;
        const size_t base = tile_base((int)T);

        float s = 0.f, sq = 0.f;
        #pragma unroll
        for (int h = 0; h < 2; h++) {
            float4 v[4];
            #pragma unroll
            for (int j = 0; j < 4; j++)
                v[j] = x4[base + (h * 4 + j) * NTHR + t];
            #pragma unroll
            for (int j = 0; j < 4; j++) {
                float2 a = fq2(v[j].x, v[j].y), d = fq2(v[j].z, v[j].w);
                s  += (a.x + a.y) + (d.x + d.y);
                sq += a.x*a.x + a.y*a.y + d.x*d.x + d.y*d.y;
            }
        }
        if (t == 0) sh_T[q ^ 1] = atomicAdd(&g_tick1, 1u);   // one-ahead grab

        #pragma unroll
        for (int o = 16; o > 0; o >>= 1) {
            s  += __shfl_down_sync(0xffffffffu, s,  o);
            sq += __shfl_down_sync(0xffffffffu, sq, o);
        }
        if (lane == 0) { sh_s[w] = s; sh_q[w] = sq; }
        __syncthreads();                     // publishes sh_s/q and sh_T[q^1]
        if (t == 0) {
            float ss = 0.f, qq = 0.f;
            #pragma unroll
            for (int i = 0; i < 8; i++) { ss += sh_s[i]; qq += sh_q[i]; }
            g_tsum[T] = ss;
            g_tsq [T] = qq;
            unsigned old;
            asm volatile("atom.acq_rel.gpu.global.add.u32 %0, [%1], %2;"
                         : "=r"(old) : "l"(&g_cnt[c]), "r"(1u) : "memory");
            sh_fin = (old == TPC - 1) ? c : -1;
        }
        __syncthreads();                     // publishes sh_fin
        const int fc = sh_fin;
        if (fc >= 0 && w == 0) {             // warp 0 finalizes channel fc
            float ss = 0.f, qq = 0.f;
            #pragma unroll
            for (int i = 0; i < 4; i++) {    // fixed order -> deterministic
                ss += g_tsum[fc * TPC + lane * 4 + i];
                qq += g_tsq [fc * TPC + lane * 4 + i];
            }
            #pragma unroll
            for (int o = 16; o > 0; o >>= 1) {
                ss += __shfl_down_sync(0xffffffffu, ss, o);
                qq += __shfl_down_sync(0xffffffffu, qq, o);
            }
            if (lane == 0) {
                const float inv_n = 1.0f / (float)CPC;
                float mean = ss * inv_n;
                float var  = qq * inv_n - mean * mean;
                float mean_q  = fq1(mean);
                float var_q   = fq1(var);
                float inv_std = 1.0f / sqrtf(var_q + 1e-5f);
                g_params[fc] = make_float4(mean_q, inv_std,
                                           fq1(weight[fc]), fq1(bias[fc]));
                asm volatile("st.release.gpu.global.u32 [%0], %1;"
                             :: "l"(&g_flag[fc]), "r"(1u) : "memory");
            }
        }
    }

    // ---------------- Phase 2: exact-reverse tile sweep (dynamic) ----------------
    if (t == 0) sh_T[0] = atomicAdd(&g_tick2, 1u);
    __syncthreads();

    for (int it = 0; ; it++) {
        const int q = it & 1;
        const unsigned U = sh_T[q];
        if (U >= NT) break;
        const int T = (NT - 1) - (int)U;     // reverse order: freshest L2 first
        const int c = T >> 7;
        const size_t base = tile_base(T);

        float4 va[4];                        // pre-issue loads (hide flag spin)
        #pragma unroll
        for (int j = 0; j < 4; j++)
            va[j] = __ldcs(x4 + base + j * NTHR + t);

        if (t == 0) {
            sh_T[q ^ 1] = atomicAdd(&g_tick2, 1u);
            unsigned f;
            for (;;) {
                asm volatile("ld.acquire.gpu.global.u32 %0, [%1];"
                             : "=r"(f) : "l"(&g_flag[c]) : "memory");
                if (f) break;
                __nanosleep(64);
            }
            sh_p[q] = g_params[c];
        }
        __syncthreads();                     // publishes sh_p[q] and sh_T[q^1]
        const float4 p = sh_p[q];            // {mean, inv_std, w, b}

        #pragma unroll
        for (int j = 0; j < 4; j++) {
            float2 a = fq2(va[j].x, va[j].y), d = fq2(va[j].z, va[j].w);
            float y0 = fmaf(p.z, (a.x - p.x) * p.y, p.w);
            float y1 = fmaf(p.z, (a.y - p.x) * p.y, p.w);
            float y2 = fmaf(p.z, (d.x - p.x) * p.y, p.w);
            float y3 = fmaf(p.z, (d.y - p.x) * p.y, p.w);
            float2 q0 = fq2(y0, y1), q1 = fq2(y2, y3);
            __stcs(o4 + base + j * NTHR + t, make_float4(q0.x, q0.y, q1.x, q1.y));
        }
        float4 vb[4];
        #pragma unroll
        for (int j = 0; j < 4; j++)
            vb[j] = __ldcs(x4 + base + (4 + j) * NTHR + t);
        #pragma unroll
        for (int j = 0; j < 4; j++) {
            float2 a = fq2(vb[j].x, vb[j].y), d = fq2(vb[j].z, vb[j].w);
            float y0 = fmaf(p.z, (a.x - p.x) * p.y, p.w);
            float y1 = fmaf(p.z, (a.y - p.x) * p.y, p.w);
            float y2 = fmaf(p.z, (d.x - p.x) * p.y, p.w);
            float y3 = fmaf(p.z, (d.y - p.x) * p.y, p.w);
            float2 q0 = fq2(y0, y1), q1 = fq2(y2, y3);
            __stcs(o4 + base + (4 + j) * NTHR + t, make_float4(q0.x, q0.y, q1.x, q1.y));
        }
    }

    // -------- Exit: last block (all loops finished everywhere) resets state --------
    if (t == 0) {
        unsigned old = atomicAdd(&g_fin, 1u);
        if (old == gridDim.x - 1) {
            g_tick1 = 0u; g_tick2 = 0u; g_fin = 0u;
            #pragma unroll
            for (int i = 0; i < NC; i++) { g_cnt[i] = 0u; g_flag[i] = 0u; }
        }
    }
}

extern "C" void kernel_launch(void* const* d_in, const int* in_sizes, int n_in,
                              void* d_out, int out_size) {
    const float* x      = (const float*)d_in[0];
    const float* weight = (const float*)d_in[1];
    const float* bias   = (const float*)d_in[2];
    float* out = (float*)d_out;

    static int nblocks = 0;
    if (nblocks == 0) {
        int sms = 0;
        cudaDeviceGetAttribute(&sms, cudaDevAttrMultiProcessorCount, 0);
        nblocks = 8 * sms;
    }
    qbn_fused<<<nblocks, NTHR>>>(x, weight, bias, out);
}